// round 15
// baseline (speedup 1.0000x reference)
#include <cuda_runtime.h>
#include <math.h>

#define T_  128
#define B_  32
#define I_  128
#define H_  128
#define R_  100
#define O_  64
#define RH_ (R_*H_)       // 12800
#define COLS_ (H_*B_)     // 4096  (k*32+b) flat columns per region

typedef unsigned long long u64;

// Scratch (static device globals)
static __device__ float g_inp[(size_t)T_*R_*B_*H_];    // [T][R][b][g]
static __device__ float g_Hkb[(size_t)T_*R_*COLS_];    // [T][r][g*32+b]
static __device__ float g_msg[(size_t)R_*COLS_];       // [r][g*32+b]
static __device__ unsigned g_arrive;                   // grid-barrier counter

// ---- packed f32x2 helpers (sm_103a) ----
__device__ __forceinline__ u64 pk2(float lo, float hi){
    u64 r; asm("mov.b64 %0, {%1,%2};" : "=l"(r) : "f"(lo), "f"(hi)); return r;
}
__device__ __forceinline__ void up2(u64 v, float& lo, float& hi){
    asm("mov.b64 {%0,%1}, %2;" : "=f"(lo), "=f"(hi) : "l"(v));
}
__device__ __forceinline__ u64 fma2(u64 a, u64 b, u64 c){
    u64 d; asm("fma.rn.f32x2 %0, %1, %2, %3;" : "=l"(d) : "l"(a), "l"(b), "l"(c)); return d;
}
__device__ __forceinline__ float tanha(float x){
    float y; asm("tanh.approx.f32 %0, %1;" : "=f"(y) : "f"(x)); return y;
}

// ============================================================================
// Kernel 1: inp[t,r,b,g] = sum_i x[t,b,i]*W_ih[r,i,g] + bias[r,g]
// Also resets the grid-barrier counter.
// ============================================================================
__global__ __launch_bounds__(256) void inp_kernel(const float* __restrict__ x,
                                                  const float* __restrict__ W_ih,
                                                  const float* __restrict__ bias){
    if (blockIdx.x == 0 && blockIdx.y == 0 && threadIdx.x == 0) g_arrive = 0u;

    int r = blockIdx.x, t = blockIdx.y;
    __shared__ u64 xs[16][128];
    const float* xt = x + (size_t)t*B_*I_;
    for (int idx = threadIdx.x; idx < B_*I_; idx += 256){
        int b = idx >> 7, k = idx & 127;
        reinterpret_cast<float*>(&xs[b>>1][k])[b&1] = xt[idx];
    }
    __syncthreads();

    int gg = threadIdx.x & 63, quad = threadIdx.x >> 6;
    float bva = bias[r*H_ + gg], bvb = bias[r*H_ + gg + 64];
    u64 acc[8];
#pragma unroll
    for (int p=0;p<4;p++){ acc[p*2+0] = pk2(bva,bva); acc[p*2+1] = pk2(bvb,bvb); }

    const float* W = W_ih + (size_t)r*I_*H_;
#pragma unroll 4
    for (int k=0;k<I_;k++){
        float wa = W[(size_t)k*H_ + gg];
        float wb = W[(size_t)k*H_ + gg + 64];
        u64 wad = pk2(wa,wa), wbd = pk2(wb,wb);
#pragma unroll
        for (int p=0;p<4;p++){
            u64 xv = xs[quad*4+p][k];
            acc[p*2+0] = fma2(xv, wad, acc[p*2+0]);
            acc[p*2+1] = fma2(xv, wbd, acc[p*2+1]);
        }
    }
    float* op = g_inp + (size_t)(t*R_ + r)*B_*H_;
#pragma unroll
    for (int p=0;p<4;p++){
        int b0 = quad*8 + 2*p;
#pragma unroll
        for (int e=0;e<2;e++){
            float lo, hi; up2(acc[p*2+e], lo, hi);
            op[b0*H_     + gg + e*64] = lo;
            op[(b0+1)*H_ + gg + e*64] = hi;
        }
    }
}

// ============================================================================
// Persistent recurrent kernel (single launch): grid = 100, 512 threads.
// smem: W_hh[r] | W_rhh[r] | C | hT | mT
// ============================================================================
#define SM_W1   0
#define SM_W2   16384
#define SM_C    32768
#define SM_HT   42768          // 4096 floats [k*32+b]
#define SM_MT   46864          // 4096 floats
#define SM_FLOATS 50960        // 203840 bytes

// Barrier: REDG arrival (no return trip) + tight-spin poll.
__device__ __forceinline__ void gbar(unsigned target){
    __threadfence();
    __syncthreads();
    if (threadIdx.x == 0){
        asm volatile("red.global.gpu.add.u32 [%0], %1;"
                     :: "l"(&g_arrive), "r"(1u) : "memory");
        volatile unsigned* va = &g_arrive;
        while (*va < target) { }
        __threadfence();
    }
    __syncthreads();
}

// phase A body: NJP j-pairs, 2 cols (c, c+32); H read directly from L2.
template<int NJP>
__device__ __forceinline__ void msg_body(const float* __restrict__ Cs,
                                         const float* __restrict__ Hb,
                                         int jp0, int col0c){
    u64 acc[NJP*2];
#pragma unroll
    for (int j=0;j<NJP*2;j++) acc[j] = 0ull;
#pragma unroll 4
    for (int i=0;i<R_;i++){
        float h0 = __ldcg(Hb + (size_t)i*COLS_);        // coalesced over c
        float h1 = __ldcg(Hb + (size_t)i*COLS_ + 32);
        u64 h0d = pk2(h0,h0), h1d = pk2(h1,h1);
        const float* Cr = Cs + i*R_ + jp0*2;
#pragma unroll
        for (int j=0;j<NJP;j++){
            u64 Cv = *reinterpret_cast<const u64*>(Cr + 2*j);   // {C[i,j],C[i,j+1]}
            acc[j*2+0] = fma2(Cv, h0d, acc[j*2+0]);
            acc[j*2+1] = fma2(Cv, h1d, acc[j*2+1]);
        }
    }
#pragma unroll
    for (int j=0;j<NJP;j++){
        int jj = (jp0 + j)*2;
#pragma unroll
        for (int e=0;e<2;e++){
            float lo, hi; up2(acc[j*2+e], lo, hi);
            int col = col0c + e*32;
            __stcg(&g_msg[(size_t)jj*COLS_     + col], lo);
            __stcg(&g_msg[(size_t)(jj+1)*COLS_ + col], hi);
        }
    }
}

__global__ __launch_bounds__(512,1) void rnn_persist(const float* __restrict__ W_hh,
                                                     const float* __restrict__ W_rhh,
                                                     const float* __restrict__ C){
    extern __shared__ float sm[];
    float* w1 = sm + SM_W1;
    float* w2 = sm + SM_W2;
    float* Cs = sm + SM_C;
    float* hT = sm + SM_HT;
    float* mT = sm + SM_MT;

    const int r = blockIdx.x, tid = threadIdx.x;

    // stage region weights + connectome once
    {
        const float4* a  = reinterpret_cast<const float4*>(W_hh  + (size_t)r*H_*H_);
        const float4* bb = reinterpret_cast<const float4*>(W_rhh + (size_t)r*H_*H_);
        float4* d1 = reinterpret_cast<float4*>(w1);
        float4* d2 = reinterpret_cast<float4*>(w2);
        for (int i=tid;i<4096;i+=512){ d1[i]=a[i]; d2[i]=bb[i]; }
        const float4* c4 = reinterpret_cast<const float4*>(C);
        float4* dc = reinterpret_cast<float4*>(Cs);
        for (int i=tid;i<2500;i+=512) dc[i]=c4[i];
    }

    // phase-B mapping: gg -> g-cols {gg, gg+64}; bq -> b0..b0+3 (2 pairs)
    const int gg = tid & 63;
    const int bq = tid >> 6;
    const int b0 = bq*4;
    // phase-A mapping
    const int c  = tid & 31;
    const int jg = tid >> 5;
    const int jp0 = (jg<2)? jg*4 : 8 + (jg-2)*3;

    unsigned bars = 0;

    for (int t = 0; t < T_; t++){
        // ---------------- phase A: msg strips (blocks 0..63) ----------------
        if (t > 0){
            if (r < 64){
                const int col0 = r*64;
                const float* Hb = g_Hkb + (size_t)(t-1)*R_*COLS_ + col0 + c;
                if (jg < 2) msg_body<4>(Cs, Hb, jp0, col0 + c);
                else        msg_body<3>(Cs, Hb, jp0, col0 + c);
            }
            gbar(++bars * (unsigned)R_);
        }

        // ---------------- phase B ----------------
        u64 acc[4];
        {
            const float* ip = g_inp + ((size_t)t*R_ + r)*B_*H_;
#pragma unroll
            for (int pp=0;pp<2;pp++){
#pragma unroll
                for (int e=0;e<2;e++){
                    int g = gg + e*64, b = b0 + 2*pp;
                    acc[pp*2+e] = pk2(ip[b*H_ + g], ip[(b+1)*H_ + g]);
                }
            }
        }
        if (t > 0){
            const float4* Hp4 = reinterpret_cast<const float4*>(g_Hkb + ((size_t)(t-1)*R_ + r)*COLS_);
            const float4* Mp4 = reinterpret_cast<const float4*>(g_msg + (size_t)r*COLS_);
            float4* hT4 = reinterpret_cast<float4*>(hT);
            float4* mT4 = reinterpret_cast<float4*>(mT);
            for (int i=tid;i<1024;i+=512){ hT4[i] = __ldcg(Hp4+i); mT4[i] = __ldcg(Mp4+i); }
            __syncthreads();
#pragma unroll 4
            for (int k=0;k<H_;k++){
                float w1a = w1[k*H_ + gg], w1b = w1[k*H_ + gg + 64];
                float w2a = w2[k*H_ + gg], w2b = w2[k*H_ + gg + 64];
                u64 w1ad = pk2(w1a,w1a), w1bd = pk2(w1b,w1b);
                u64 w2ad = pk2(w2a,w2a), w2bd = pk2(w2b,w2b);
                ulonglong2 hA = *reinterpret_cast<const ulonglong2*>(hT + k*32 + b0);
                ulonglong2 mA = *reinterpret_cast<const ulonglong2*>(mT + k*32 + b0);
                acc[0] = fma2(hA.x, w1ad, acc[0]);  acc[0] = fma2(mA.x, w2ad, acc[0]);
                acc[1] = fma2(hA.x, w1bd, acc[1]);  acc[1] = fma2(mA.x, w2bd, acc[1]);
                acc[2] = fma2(hA.y, w1ad, acc[2]);  acc[2] = fma2(mA.y, w2ad, acc[2]);
                acc[3] = fma2(hA.y, w1bd, acc[3]);  acc[3] = fma2(mA.y, w2bd, acc[3]);
            }
            __syncthreads();   // hT/mT free for next step
        }
        {
            float* Hkb = g_Hkb + ((size_t)t*R_ + r)*COLS_;
#pragma unroll
            for (int pp=0;pp<2;pp++){
#pragma unroll
                for (int e=0;e<2;e++){
                    float lo, hi; up2(acc[pp*2+e], lo, hi);
                    int g = gg + e*64, b = b0 + 2*pp;
                    __stcg(reinterpret_cast<float2*>(Hkb + g*32 + b),
                           make_float2(tanha(lo), tanha(hi)));
                }
            }
        }
        if (t < T_-1) gbar(++bars * (unsigned)R_);
    }
}

// ============================================================================
// Kernel 3: out[t,b,o] = H[t][b][:] @ W_out + b_out   grid (T,2), 128 thr
// Reads g_Hkb layout: H[t][b][r*128+g] = Hkb[t][r][g*32+b].
// ============================================================================
__global__ __launch_bounds__(128) void out_kernel(const float* __restrict__ W_out,
                                                  const float* __restrict__ b_out,
                                                  float* __restrict__ out){
    int t = blockIdx.x, bh = blockIdx.y;            // rows [bh*16, bh*16+16)
    __shared__ u64 hsh[128][9];                     // [g][b-pair], 18 floats/row
    int tid = threadIdx.x;
    int og = tid & 15, rp = tid >> 4;
    int o0 = og*4;
    u64 acc[4];
    {
        const u64* bo = reinterpret_cast<const u64*>(b_out + o0);
        acc[0]=bo[0]; acc[1]=bo[1]; acc[2]=bo[0]; acc[3]=bo[1];
    }
    const float* Hb = g_Hkb + (size_t)t*R_*COLS_;   // [r][g*32+b]
    for (int rt=0; rt<R_; rt++){
        const float* tile = Hb + (size_t)rt*COLS_ + bh*16;
        __syncthreads();
        for (int idx = tid; idx < 16*128; idx += 128){
            int g = idx >> 4, bb = idx & 15;
            reinterpret_cast<float*>(&hsh[g][bb>>1])[bb&1] = __ldcg(tile + g*32 + bb);
        }
        __syncthreads();
#pragma unroll 4
        for (int kk=0; kk<128; kk++){
            int k = rt*128 + kk;                    // W_out row index r*H+g
            ulonglong2 w = *reinterpret_cast<const ulonglong2*>(W_out + (size_t)k*O_ + o0);
            u64 hp = hsh[kk][rp];
            float h0, h1; up2(hp, h0, h1);
            u64 h0d = pk2(h0,h0), h1d = pk2(h1,h1);
            acc[0] = fma2(w.x, h0d, acc[0]);  acc[1] = fma2(w.y, h0d, acc[1]);
            acc[2] = fma2(w.x, h1d, acc[2]);  acc[3] = fma2(w.y, h1d, acc[3]);
        }
    }
    u64* op = reinterpret_cast<u64*>(out);
    int row0 = bh*16 + rp*2;
    size_t base0 = ((size_t)(t*B_ + row0  )*O_ + o0) >> 1;
    size_t base1 = ((size_t)(t*B_ + row0+1)*O_ + o0) >> 1;
    op[base0] = acc[0];  op[base0+1] = acc[1];
    op[base1] = acc[2];  op[base1+1] = acc[3];
}

// Profiling alignment pads.
__global__ void pad_kernel(){ }

// ============================================================================
// Launch: inp, 3x pad, rnn_persist, out.
// ============================================================================
extern "C" void kernel_launch(void* const* d_in, const int* in_sizes, int n_in,
                              void* d_out, int out_size){
    const float* x     = (const float*)d_in[0];
    const float* C     = (const float*)d_in[1];
    const float* W_ih  = (const float*)d_in[2];
    const float* W_hh  = (const float*)d_in[3];
    const float* W_rhh = (const float*)d_in[4];
    const float* bias  = (const float*)d_in[5];
    const float* W_out = (const float*)d_in[6];
    const float* b_out = (const float*)d_in[7];
    float* out = (float*)d_out;

    cudaFuncSetAttribute(rnn_persist, cudaFuncAttributeMaxDynamicSharedMemorySize,
                         SM_FLOATS * (int)sizeof(float));

    inp_kernel<<<dim3(R_, T_), 256>>>(x, W_ih, bias);     // resets g_arrive
    pad_kernel<<<1, 32>>>();
    pad_kernel<<<1, 32>>>();
    pad_kernel<<<1, 32>>>();
    rnn_persist<<<R_, 512, SM_FLOATS * sizeof(float)>>>(W_hh, W_rhh, C);
    out_kernel<<<dim3(T_, 2), 128>>>(W_out, b_out, out);
}

// round 16
// speedup vs baseline: 1.3626x; 1.3626x over previous
#include <cuda_runtime.h>
#include <math.h>

#define T_  128
#define B_  32
#define I_  128
#define H_  128
#define R_  100
#define O_  64
#define RH_ (R_*H_)   // 12800

typedef unsigned long long u64;

// Scratch (static device globals)
static __device__ float g_inp[(size_t)T_*R_*B_*H_];   // [T][R][B][H]
static __device__ float g_H  [(size_t)T_*B_*RH_];     // [T][B][R*H]
static __device__ float g_msg[(size_t)R_*B_*H_];      // [R][B][H]
static __device__ unsigned g_arrive;                  // grid-barrier counter

// ---- packed f32x2 helpers (sm_103a) ----
__device__ __forceinline__ u64 pk2(float lo, float hi){
    u64 r; asm("mov.b64 %0, {%1,%2};" : "=l"(r) : "f"(lo), "f"(hi)); return r;
}
__device__ __forceinline__ void up2(u64 v, float& lo, float& hi){
    asm("mov.b64 {%0,%1}, %2;" : "=f"(lo), "=f"(hi) : "l"(v));
}
__device__ __forceinline__ u64 fma2(u64 a, u64 b, u64 c){
    u64 d; asm("fma.rn.f32x2 %0, %1, %2, %3;" : "=l"(d) : "l"(a), "l"(b), "l"(c)); return d;
}
__device__ __forceinline__ float tanha(float x){
    float y; asm("tanh.approx.f32 %0, %1;" : "=f"(y) : "f"(x)); return y;
}

// ============================================================================
// Kernel 1: inp[t,r,b,h] = sum_i x[t,b,i]*W_ih[r,i,h] + bias[r,h]
// Also resets the grid-barrier counter (runs before the persistent kernel).
// ============================================================================
__global__ __launch_bounds__(256) void inp_kernel(const float* __restrict__ x,
                                                  const float* __restrict__ W_ih,
                                                  const float* __restrict__ bias){
    if (blockIdx.x == 0 && blockIdx.y == 0 && threadIdx.x == 0) g_arrive = 0u;

    int r = blockIdx.x, t = blockIdx.y;
    __shared__ u64 xs[16][128];                       // {x[2bb][k], x[2bb+1][k]}
    const float* xt = x + (size_t)t*B_*I_;
    for (int idx = threadIdx.x; idx < B_*I_; idx += 256){
        int b = idx >> 7, k = idx & 127;
        reinterpret_cast<float*>(&xs[b>>1][k])[b&1] = xt[idx];
    }
    __syncthreads();
    int g = threadIdx.x & 127, half = threadIdx.x >> 7;
    float bv = bias[r*H_ + g];
    u64 binit = pk2(bv, bv);
    u64 acc[8];
#pragma unroll
    for (int p=0;p<8;p++) acc[p] = binit;
    const float* W = W_ih + (size_t)r*I_*H_ + g;
#pragma unroll 4
    for (int k=0;k<I_;k++){
        float w = W[(size_t)k*H_];
        u64 w2 = pk2(w, w);
#pragma unroll
        for (int p=0;p<8;p++) acc[p] = fma2(xs[half*8+p][k], w2, acc[p]);
    }
    float* op = g_inp + (size_t)(t*R_ + r)*B_*H_;
#pragma unroll
    for (int p=0;p<8;p++){
        int b0 = half*16 + 2*p;
        float lo, hi; up2(acc[p], lo, hi);
        op[b0*H_ + g]     = lo;
        op[(b0+1)*H_ + g] = hi;
    }
}

// ============================================================================
// Persistent recurrent kernel: grid = 100 blocks, 512 threads.
// smem: W_hh[r] | W_rhh[r] | C | hT | mT   (Hs for msg overlays hT/mT)
// ============================================================================
#define SM_W1   0
#define SM_W2   16384
#define SM_C    32768
#define SM_HT   42768          // 128 rows x 36 floats
#define SM_MT   47376
#define SM_FLOATS 51984        // 207936 bytes

__device__ __forceinline__ void gbar(unsigned target){
    __threadfence();
    __syncthreads();
    if (threadIdx.x == 0){
        atomicAdd(&g_arrive, 1u);
        volatile unsigned* va = &g_arrive;
        while (*va < target) { }
    }
    __syncthreads();
}

// msg inner body: NP j-pairs, 2 h-columns (c0, c0+1)
template<int NP>
__device__ __forceinline__ void msg_body(const float* __restrict__ Cs,
                                         const float* __restrict__ Hs,
                                         int c0, int jp0, int b, int hh){
    u64 acc[NP*2];
#pragma unroll
    for (int j=0;j<NP*2;j++) acc[j] = 0ull;
#pragma unroll 2
    for (int i=0;i<R_;i++){
        float2 hp = *reinterpret_cast<const float2*>(Hs + i*64 + c0);
        u64 h0 = pk2(hp.x, hp.x), h1 = pk2(hp.y, hp.y);
        const float* Cr = Cs + i*R_ + jp0*2;
#pragma unroll
        for (int j=0;j<NP;j++){
            u64 cv = *reinterpret_cast<const u64*>(Cr + 2*j);  // broadcast LDS.64
            acc[j*2+0] = fma2(cv, h0, acc[j*2+0]);
            acc[j*2+1] = fma2(cv, h1, acc[j*2+1]);
        }
    }
#pragma unroll
    for (int j=0;j<NP;j++){
        int jA = jp0*2 + 2*j, jB = jA + 1;
#pragma unroll
        for (int cc=0;cc<2;cc++){
            float lo, hi; up2(acc[j*2+cc], lo, hi);
            int col = hh*64 + c0 + cc;
            __stcg(&g_msg[(size_t)jA*B_*H_ + b*H_ + col], lo);
            __stcg(&g_msg[(size_t)jB*B_*H_ + b*H_ + col], hi);
        }
    }
}

__global__ __launch_bounds__(512,1) void rnn_persist(const float* __restrict__ W_hh,
                                                     const float* __restrict__ W_rhh,
                                                     const float* __restrict__ C){
    extern __shared__ float sm[];
    float* w1 = sm + SM_W1;
    float* w2 = sm + SM_W2;
    float* Cs = sm + SM_C;
    float* hT = sm + SM_HT;
    float* mT = sm + SM_MT;
    float* Hs = hT;                       // overlay for msg phase (6400 floats)

    const int r = blockIdx.x, tid = threadIdx.x;

    // one-time staging: region weights + connectome
    {
        const float4* a  = reinterpret_cast<const float4*>(W_hh  + (size_t)r*H_*H_);
        const float4* bb = reinterpret_cast<const float4*>(W_rhh + (size_t)r*H_*H_);
        float4* d1 = reinterpret_cast<float4*>(w1);
        float4* d2 = reinterpret_cast<float4*>(w2);
        for (int i=tid;i<4096;i+=512){ d1[i]=a[i]; d2[i]=bb[i]; }
        const float4* c4 = reinterpret_cast<const float4*>(C);
        float4* dc = reinterpret_cast<float4*>(Cs);
        for (int i=tid;i<2500;i+=512) dc[i]=c4[i];
    }

    // phase-B mapping: 2 g-cols x 2 b-pairs per thread
    const int gg = tid & 63;
    const int bq = tid >> 6;              // 0..7
    const int b0 = bq*4;                  // 4 b's = 2 pairs
    // phase-A mapping: 2 h-cols x (3..4) j-pairs
    const int cg = tid & 31, c0 = cg*2;
    const int jg = tid >> 5;              // 0..15
    const int jp0 = (jg<2)? jg*4 : 8 + (jg-2)*3;

    unsigned bars = 0;

    for (int t = 0; t < T_; t++){
        // ------------- phase A: msg (blocks 0..63) -------------
        if (t > 0){
            if (r < 64){
                int b  = r >> 1, hh = r & 1;
                const float* Hp = g_H + ((size_t)(t-1)*B_ + b)*RH_ + hh*64;
                for (int idx=tid; idx<6400; idx+=512)
                    Hs[idx] = __ldcg(Hp + (size_t)(idx>>6)*H_ + (idx&63));
                __syncthreads();
                if (jg < 2) msg_body<4>(Cs, Hs, c0, jp0, b, hh);
                else        msg_body<3>(Cs, Hs, c0, jp0, b, hh);
            }
            gbar(++bars * (unsigned)R_);
        }

        // ------------- phase B: H[t] = tanh(inp + loc + cross) -------------
        u64 acc[4];
        {
            const float* ip = g_inp + ((size_t)t*R_ + r)*B_*H_;
#pragma unroll
            for (int p=0;p<2;p++){
#pragma unroll
                for (int e=0;e<2;e++){
                    int g = gg + e*64;
                    acc[p*2+e] = pk2(ip[(b0+2*p)*H_ + g], ip[(b0+2*p+1)*H_ + g]);
                }
            }
        }
        if (t > 0){
            const float* Hp = g_H  + (size_t)(t-1)*B_*RH_ + (size_t)r*H_;
            const float* Mp = g_msg + (size_t)r*B_*H_;
            for (int idx=tid; idx<4096; idx+=512){
                int b = idx >> 7, k = idx & 127;
                hT[k*36 + b] = __ldcg(Hp + (size_t)b*RH_ + k);
                mT[k*36 + b] = __ldcg(Mp + idx);
            }
            __syncthreads();
#pragma unroll 4
            for (int k=0;k<H_;k++){
                float w1a = w1[k*H_ + gg], w1b = w1[k*H_ + gg + 64];
                float w2a = w2[k*H_ + gg], w2b = w2[k*H_ + gg + 64];
                u64 w1ad = pk2(w1a,w1a), w1bd = pk2(w1b,w1b);
                u64 w2ad = pk2(w2a,w2a), w2bd = pk2(w2b,w2b);
                ulonglong2 hA = *reinterpret_cast<const ulonglong2*>(hT + k*36 + b0);
                ulonglong2 mA = *reinterpret_cast<const ulonglong2*>(mT + k*36 + b0);
                acc[0] = fma2(hA.x, w1ad, acc[0]);  acc[0] = fma2(mA.x, w2ad, acc[0]);
                acc[1] = fma2(hA.x, w1bd, acc[1]);  acc[1] = fma2(mA.x, w2bd, acc[1]);
                acc[2] = fma2(hA.y, w1ad, acc[2]);  acc[2] = fma2(mA.y, w2ad, acc[2]);
                acc[3] = fma2(hA.y, w1bd, acc[3]);  acc[3] = fma2(mA.y, w2bd, acc[3]);
            }
        }
        {
            float* Ho = g_H + (size_t)t*B_*RH_ + (size_t)r*H_;
#pragma unroll
            for (int p=0;p<2;p++){
#pragma unroll
                for (int e=0;e<2;e++){
                    float lo, hi; up2(acc[p*2+e], lo, hi);
                    int g = gg + e*64;
                    __stcg(Ho + (size_t)(b0+2*p)*RH_   + g, tanha(lo));
                    __stcg(Ho + (size_t)(b0+2*p+1)*RH_ + g, tanha(hi));
                }
            }
        }
        if (t < T_-1) gbar(++bars * (unsigned)R_);
    }
}

// ============================================================================
// Kernel 3: out[t,b,o] = H[t][b][:] @ W_out + b_out   grid (T,2), 128 thr
// ============================================================================
__global__ __launch_bounds__(128) void out_kernel(const float* __restrict__ W_out,
                                                  const float* __restrict__ b_out,
                                                  float* __restrict__ out){
    int t = blockIdx.x, bh = blockIdx.y;             // bh: rows [bh*16, bh*16+16)
    __shared__ u64 hsh[128][9];                      // [kk][row-pair], padded
    int tid = threadIdx.x;
    int og = tid & 15, rp = tid >> 4;                // og*4 = o0 ; rp: row-pair 0..7
    int o0 = og*4;
    u64 acc[4];                                      // [row 0/1][o-pair 0/1]
    {
        const u64* bo = reinterpret_cast<const u64*>(b_out + o0);
        acc[0]=bo[0]; acc[1]=bo[1]; acc[2]=bo[0]; acc[3]=bo[1];
    }
    const float* Hb = g_H + (size_t)t*B_*RH_ + (size_t)(bh*16)*RH_;
    for (int kt=0; kt<RH_/128; kt++){
        __syncthreads();
        for (int idx = tid; idx < 16*128; idx += 128){
            int b = idx >> 7, kk = idx & 127;
            reinterpret_cast<float*>(&hsh[kk][b>>1])[b&1] = Hb[(size_t)b*RH_ + kt*128 + kk];
        }
        __syncthreads();
#pragma unroll 4
        for (int kk=0; kk<128; kk++){
            int k = kt*128 + kk;
            ulonglong2 w = *reinterpret_cast<const ulonglong2*>(W_out + (size_t)k*O_ + o0);
            u64 hp = hsh[kk][rp];
            float h0, h1; up2(hp, h0, h1);
            u64 h0d = pk2(h0,h0), h1d = pk2(h1,h1);
            acc[0] = fma2(w.x, h0d, acc[0]);  acc[1] = fma2(w.y, h0d, acc[1]);
            acc[2] = fma2(w.x, h1d, acc[2]);  acc[3] = fma2(w.y, h1d, acc[3]);
        }
    }
    u64* op = reinterpret_cast<u64*>(out);
    int row0 = bh*16 + rp*2;
    size_t base0 = ((size_t)(t*B_ + row0  )*O_ + o0) >> 1;
    size_t base1 = ((size_t)(t*B_ + row0+1)*O_ + o0) >> 1;
    op[base0] = acc[0];  op[base0+1] = acc[1];
    op[base1] = acc[2];  op[base1+1] = acc[3];
}

// ============================================================================
// Launch
// ============================================================================
extern "C" void kernel_launch(void* const* d_in, const int* in_sizes, int n_in,
                              void* d_out, int out_size){
    const float* x     = (const float*)d_in[0];
    const float* C     = (const float*)d_in[1];
    const float* W_ih  = (const float*)d_in[2];
    const float* W_hh  = (const float*)d_in[3];
    const float* W_rhh = (const float*)d_in[4];
    const float* bias  = (const float*)d_in[5];
    const float* W_out = (const float*)d_in[6];
    const float* b_out = (const float*)d_in[7];
    float* out = (float*)d_out;

    cudaFuncSetAttribute(rnn_persist, cudaFuncAttributeMaxDynamicSharedMemorySize,
                         SM_FLOATS * (int)sizeof(float));

    inp_kernel<<<dim3(R_, T_), 256>>>(x, W_ih, bias);     // resets g_arrive
    rnn_persist<<<R_, 512, SM_FLOATS * sizeof(float)>>>(W_hh, W_rhh, C);
    out_kernel<<<dim3(T_, 2), 128>>>(W_out, b_out, out);
}

// round 17
// speedup vs baseline: 1.3781x; 1.0114x over previous
#include <cuda_runtime.h>
#include <math.h>

#define T_  128
#define B_  32
#define I_  128
#define H_  128
#define R_  100
#define O_  64
#define RH_ (R_*H_)   // 12800

typedef unsigned long long u64;

// Scratch (static device globals)
static __device__ float g_inp[(size_t)T_*R_*B_*H_];   // [T][R][B][H]
static __device__ float g_H  [(size_t)T_*B_*RH_];     // [T][B][R*H]
static __device__ float g_msg[(size_t)R_*B_*H_];      // [R][B][H]
static __device__ unsigned g_arrive;                  // grid-barrier counter

// ---- packed f32x2 helpers (sm_103a) ----
__device__ __forceinline__ u64 pk2(float lo, float hi){
    u64 r; asm("mov.b64 %0, {%1,%2};" : "=l"(r) : "f"(lo), "f"(hi)); return r;
}
__device__ __forceinline__ void up2(u64 v, float& lo, float& hi){
    asm("mov.b64 {%0,%1}, %2;" : "=f"(lo), "=f"(hi) : "l"(v));
}
__device__ __forceinline__ u64 fma2(u64 a, u64 b, u64 c){
    u64 d; asm("fma.rn.f32x2 %0, %1, %2, %3;" : "=l"(d) : "l"(a), "l"(b), "l"(c)); return d;
}
__device__ __forceinline__ float tanha(float x){
    float y; asm("tanh.approx.f32 %0, %1;" : "=f"(y) : "f"(x)); return y;
}

// ============================================================================
// Kernel 1 (4:1 fma2:LDS): inp[t,r,b,g] = bias + sum_i x[t,b,i]*W_ih[r,i,g]
// 128 thr: thread owns 4 g-cols {gg,+32,+64,+96} x 4 b-pairs. Resets barrier.
// ============================================================================
__global__ __launch_bounds__(128) void inp_kernel(const float* __restrict__ x,
                                                  const float* __restrict__ W_ih,
                                                  const float* __restrict__ bias){
    if (blockIdx.x == 0 && blockIdx.y == 0 && threadIdx.x == 0) g_arrive = 0u;

    int r = blockIdx.x, t = blockIdx.y;
    __shared__ u64 xs[16][128];                       // {x[2bp][k], x[2bp+1][k]}
    const float* xt = x + (size_t)t*B_*I_;
    for (int idx = threadIdx.x; idx < B_*I_; idx += 128){
        int b = idx >> 7, k = idx & 127;
        reinterpret_cast<float*>(&xs[b>>1][k])[b&1] = xt[idx];
    }
    __syncthreads();

    const int gg = threadIdx.x & 31;                  // g-cols gg + e*32
    const int quad = threadIdx.x >> 5;                // b-pairs quad*4 .. quad*4+3
    u64 acc[16];                                      // [e][p]
#pragma unroll
    for (int e=0;e<4;e++){
        float bv = bias[r*H_ + gg + e*32];
        u64 b2 = pk2(bv, bv);
#pragma unroll
        for (int p=0;p<4;p++) acc[e*4+p] = b2;
    }

    const float* W = W_ih + (size_t)r*I_*H_;
#pragma unroll 4
    for (int k=0;k<I_;k++){
        const float* Wk = W + (size_t)k*H_ + gg;
        float w0 = Wk[0], w1 = Wk[32], w2 = Wk[64], w3 = Wk[96];
        u64 wd0 = pk2(w0,w0), wd1 = pk2(w1,w1), wd2 = pk2(w2,w2), wd3 = pk2(w3,w3);
#pragma unroll
        for (int p=0;p<4;p++){
            u64 xv = xs[quad*4+p][k];                 // broadcast LDS.64
            acc[0*4+p] = fma2(xv, wd0, acc[0*4+p]);
            acc[1*4+p] = fma2(xv, wd1, acc[1*4+p]);
            acc[2*4+p] = fma2(xv, wd2, acc[2*4+p]);
            acc[3*4+p] = fma2(xv, wd3, acc[3*4+p]);
        }
    }
    float* op = g_inp + (size_t)(t*R_ + r)*B_*H_;
#pragma unroll
    for (int p=0;p<4;p++){
        int b0 = quad*8 + 2*p;
#pragma unroll
        for (int e=0;e<4;e++){
            float lo, hi; up2(acc[e*4+p], lo, hi);
            op[b0*H_     + gg + e*32] = lo;
            op[(b0+1)*H_ + gg + e*32] = hi;
        }
    }
}

// ============================================================================
// Persistent recurrent kernel: grid = 100 blocks, 512 threads. (R16-identical)
// smem: W_hh[r] | W_rhh[r] | C | hT | mT   (Hs for msg overlays hT/mT)
// ============================================================================
#define SM_W1   0
#define SM_W2   16384
#define SM_C    32768
#define SM_HT   42768          // 128 rows x 36 floats
#define SM_MT   47376
#define SM_FLOATS 51984        // 207936 bytes

__device__ __forceinline__ void gbar(unsigned target){
    __threadfence();
    __syncthreads();
    if (threadIdx.x == 0){
        atomicAdd(&g_arrive, 1u);
        volatile unsigned* va = &g_arrive;
        while (*va < target) { }
    }
    __syncthreads();
}

// msg inner body: NP j-pairs, 2 h-columns (c0, c0+1)
template<int NP>
__device__ __forceinline__ void msg_body(const float* __restrict__ Cs,
                                         const float* __restrict__ Hs,
                                         int c0, int jp0, int b, int hh){
    u64 acc[NP*2];
#pragma unroll
    for (int j=0;j<NP*2;j++) acc[j] = 0ull;
#pragma unroll 2
    for (int i=0;i<R_;i++){
        float2 hp = *reinterpret_cast<const float2*>(Hs + i*64 + c0);
        u64 h0 = pk2(hp.x, hp.x), h1 = pk2(hp.y, hp.y);
        const float* Cr = Cs + i*R_ + jp0*2;
#pragma unroll
        for (int j=0;j<NP;j++){
            u64 cv = *reinterpret_cast<const u64*>(Cr + 2*j);  // broadcast LDS.64
            acc[j*2+0] = fma2(cv, h0, acc[j*2+0]);
            acc[j*2+1] = fma2(cv, h1, acc[j*2+1]);
        }
    }
#pragma unroll
    for (int j=0;j<NP;j++){
        int jA = jp0*2 + 2*j, jB = jA + 1;
#pragma unroll
        for (int cc=0;cc<2;cc++){
            float lo, hi; up2(acc[j*2+cc], lo, hi);
            int col = hh*64 + c0 + cc;
            __stcg(&g_msg[(size_t)jA*B_*H_ + b*H_ + col], lo);
            __stcg(&g_msg[(size_t)jB*B_*H_ + b*H_ + col], hi);
        }
    }
}

__global__ __launch_bounds__(512,1) void rnn_persist(const float* __restrict__ W_hh,
                                                     const float* __restrict__ W_rhh,
                                                     const float* __restrict__ C){
    extern __shared__ float sm[];
    float* w1 = sm + SM_W1;
    float* w2 = sm + SM_W2;
    float* Cs = sm + SM_C;
    float* hT = sm + SM_HT;
    float* mT = sm + SM_MT;
    float* Hs = hT;                       // overlay for msg phase (6400 floats)

    const int r = blockIdx.x, tid = threadIdx.x;

    // one-time staging: region weights + connectome
    {
        const float4* a  = reinterpret_cast<const float4*>(W_hh  + (size_t)r*H_*H_);
        const float4* bb = reinterpret_cast<const float4*>(W_rhh + (size_t)r*H_*H_);
        float4* d1 = reinterpret_cast<float4*>(w1);
        float4* d2 = reinterpret_cast<float4*>(w2);
        for (int i=tid;i<4096;i+=512){ d1[i]=a[i]; d2[i]=bb[i]; }
        const float4* c4 = reinterpret_cast<const float4*>(C);
        float4* dc = reinterpret_cast<float4*>(Cs);
        for (int i=tid;i<2500;i+=512) dc[i]=c4[i];
    }

    // phase-B mapping: 2 g-cols x 2 b-pairs per thread
    const int gg = tid & 63;
    const int bq = tid >> 6;              // 0..7
    const int b0 = bq*4;                  // 4 b's = 2 pairs
    // phase-A mapping: 2 h-cols x (3..4) j-pairs
    const int cg = tid & 31, c0 = cg*2;
    const int jg = tid >> 5;              // 0..15
    const int jp0 = (jg<2)? jg*4 : 8 + (jg-2)*3;

    unsigned bars = 0;

    for (int t = 0; t < T_; t++){
        // ------------- phase A: msg (blocks 0..63) -------------
        if (t > 0){
            if (r < 64){
                int b  = r >> 1, hh = r & 1;
                const float* Hp = g_H + ((size_t)(t-1)*B_ + b)*RH_ + hh*64;
                for (int idx=tid; idx<6400; idx+=512)
                    Hs[idx] = __ldcg(Hp + (size_t)(idx>>6)*H_ + (idx&63));
                __syncthreads();
                if (jg < 2) msg_body<4>(Cs, Hs, c0, jp0, b, hh);
                else        msg_body<3>(Cs, Hs, c0, jp0, b, hh);
            }
            gbar(++bars * (unsigned)R_);
        }

        // ------------- phase B: H[t] = tanh(inp + loc + cross) -------------
        u64 acc[4];
        {
            const float* ip = g_inp + ((size_t)t*R_ + r)*B_*H_;
#pragma unroll
            for (int p=0;p<2;p++){
#pragma unroll
                for (int e=0;e<2;e++){
                    int g = gg + e*64;
                    acc[p*2+e] = pk2(ip[(b0+2*p)*H_ + g], ip[(b0+2*p+1)*H_ + g]);
                }
            }
        }
        if (t > 0){
            const float* Hp = g_H  + (size_t)(t-1)*B_*RH_ + (size_t)r*H_;
            const float* Mp = g_msg + (size_t)r*B_*H_;
            for (int idx=tid; idx<4096; idx+=512){
                int b = idx >> 7, k = idx & 127;
                hT[k*36 + b] = __ldcg(Hp + (size_t)b*RH_ + k);
                mT[k*36 + b] = __ldcg(Mp + idx);
            }
            __syncthreads();
#pragma unroll 4
            for (int k=0;k<H_;k++){
                float w1a = w1[k*H_ + gg], w1b = w1[k*H_ + gg + 64];
                float w2a = w2[k*H_ + gg], w2b = w2[k*H_ + gg + 64];
                u64 w1ad = pk2(w1a,w1a), w1bd = pk2(w1b,w1b);
                u64 w2ad = pk2(w2a,w2a), w2bd = pk2(w2b,w2b);
                ulonglong2 hA = *reinterpret_cast<const ulonglong2*>(hT + k*36 + b0);
                ulonglong2 mA = *reinterpret_cast<const ulonglong2*>(mT + k*36 + b0);
                acc[0] = fma2(hA.x, w1ad, acc[0]);  acc[0] = fma2(mA.x, w2ad, acc[0]);
                acc[1] = fma2(hA.x, w1bd, acc[1]);  acc[1] = fma2(mA.x, w2bd, acc[1]);
                acc[2] = fma2(hA.y, w1ad, acc[2]);  acc[2] = fma2(mA.y, w2ad, acc[2]);
                acc[3] = fma2(hA.y, w1bd, acc[3]);  acc[3] = fma2(mA.y, w2bd, acc[3]);
            }
        }
        {
            float* Ho = g_H + (size_t)t*B_*RH_ + (size_t)r*H_;
#pragma unroll
            for (int p=0;p<2;p++){
#pragma unroll
                for (int e=0;e<2;e++){
                    float lo, hi; up2(acc[p*2+e], lo, hi);
                    int g = gg + e*64;
                    __stcg(Ho + (size_t)(b0+2*p)*RH_   + g, tanha(lo));
                    __stcg(Ho + (size_t)(b0+2*p+1)*RH_ + g, tanha(hi));
                }
            }
        }
        if (t < T_-1) gbar(++bars * (unsigned)R_);
    }
}

// ============================================================================
// Kernel 3: out[t,b,o] = H[t][b][:] @ W_out + b_out   grid (T,2), 128 thr
// ============================================================================
__global__ __launch_bounds__(128) void out_kernel(const float* __restrict__ W_out,
                                                  const float* __restrict__ b_out,
                                                  float* __restrict__ out){
    int t = blockIdx.x, bh = blockIdx.y;             // bh: rows [bh*16, bh*16+16)
    __shared__ u64 hsh[128][9];                      // [kk][row-pair], padded
    int tid = threadIdx.x;
    int og = tid & 15, rp = tid >> 4;                // og*4 = o0 ; rp: row-pair 0..7
    int o0 = og*4;
    u64 acc[4];                                      // [row 0/1][o-pair 0/1]
    {
        const u64* bo = reinterpret_cast<const u64*>(b_out + o0);
        acc[0]=bo[0]; acc[1]=bo[1]; acc[2]=bo[0]; acc[3]=bo[1];
    }
    const float* Hb = g_H + (size_t)t*B_*RH_ + (size_t)(bh*16)*RH_;
    for (int kt=0; kt<RH_/128; kt++){
        __syncthreads();
        for (int idx = tid; idx < 16*128; idx += 128){
            int b = idx >> 7, kk = idx & 127;
            reinterpret_cast<float*>(&hsh[kk][b>>1])[b&1] = Hb[(size_t)b*RH_ + kt*128 + kk];
        }
        __syncthreads();
#pragma unroll 4
        for (int kk=0; kk<128; kk++){
            int k = kt*128 + kk;
            ulonglong2 w = *reinterpret_cast<const ulonglong2*>(W_out + (size_t)k*O_ + o0);
            u64 hp = hsh[kk][rp];
            float h0, h1; up2(hp, h0, h1);
            u64 h0d = pk2(h0,h0), h1d = pk2(h1,h1);
            acc[0] = fma2(w.x, h0d, acc[0]);  acc[1] = fma2(w.y, h0d, acc[1]);
            acc[2] = fma2(w.x, h1d, acc[2]);  acc[3] = fma2(w.y, h1d, acc[3]);
        }
    }
    u64* op = reinterpret_cast<u64*>(out);
    int row0 = bh*16 + rp*2;
    size_t base0 = ((size_t)(t*B_ + row0  )*O_ + o0) >> 1;
    size_t base1 = ((size_t)(t*B_ + row0+1)*O_ + o0) >> 1;
    op[base0] = acc[0];  op[base0+1] = acc[1];
    op[base1] = acc[2];  op[base1+1] = acc[3];
}

// ============================================================================
// Launch
// ============================================================================
extern "C" void kernel_launch(void* const* d_in, const int* in_sizes, int n_in,
                              void* d_out, int out_size){
    const float* x     = (const float*)d_in[0];
    const float* C     = (const float*)d_in[1];
    const float* W_ih  = (const float*)d_in[2];
    const float* W_hh  = (const float*)d_in[3];
    const float* W_rhh = (const float*)d_in[4];
    const float* bias  = (const float*)d_in[5];
    const float* W_out = (const float*)d_in[6];
    const float* b_out = (const float*)d_in[7];
    float* out = (float*)d_out;

    cudaFuncSetAttribute(rnn_persist, cudaFuncAttributeMaxDynamicSharedMemorySize,
                         SM_FLOATS * (int)sizeof(float));

    inp_kernel<<<dim3(R_, T_), 128>>>(x, W_ih, bias);     // resets g_arrive
    rnn_persist<<<R_, 512, SM_FLOATS * sizeof(float)>>>(W_hh, W_rhh, C);
    out_kernel<<<dim3(T_, 2), 128>>>(W_out, b_out, out);
}